// round 7
// baseline (speedup 1.0000x reference)
#include <cuda_runtime.h>

#define NB 16
#define NH 16
#define NI 512
#define NE 512
#define IE (NI * NE)
#define JSPLIT 8

// emb partials (device scratch; allocations forbidden)
__device__ float g_embp[JSPLIT][NB * NH * NE];  // 4 MB

// ---------------------------------------------------------------------------
// Kernel 1: emb partials. g_embp[js][b,h,e] = sum_{j in 64-slice} x[b,j,e]*Wv[h,j,e]
// Block covers ALL 16b x 16h x 16e x 64j -> x and Wv each hit L2 exactly once
// chip-wide (32 MB total, the floor). Grid 256 = 32 e-chunks x 8 j-splits.
// Operands staged in double-buffered smem (8 j per chunk); thread tile 4b x 4h
// (16 acc regs). Per j: 8 LDS.32 + 16 FMA. Also bias-inits the output.
// ---------------------------------------------------------------------------
__global__ __launch_bounds__(256) void emb_kernel(const float* __restrict__ x,
                                                  const float* __restrict__ wv,
                                                  const float* __restrict__ bias,
                                                  float* __restrict__ out) {
    const int t   = threadIdx.x;
    const int bid = blockIdx.x;        // 256 blocks

    // Bias init (gemm accumulates on top).
    {
        const int oidx = bid * 256 + t;            // 0 .. 65535
        const float bv = bias[oidx & (NE - 1)];
        out[oidx]         = bv;
        out[oidx + 65536] = bv;
    }

    const int ec = bid & 31;           // e chunk (16 e)
    const int js = bid >> 5;           // j split (64 j)
    const int e0 = ec * 16;
    const int j0 = js * 64;

    // consumer mapping
    const int el = t & 15;             // e lane
    const int grp = t >> 4;            // 16 groups
    const int b0 = (grp & 3) * 4;
    const int h0 = (grp >> 2) * 4;

    // producer mapping (one float4 per thread per r)
    const int pe4 = t & 3;             // e float4 (16e = 4)
    const int pj  = (t >> 2) & 7;      // j within chunk
    const int pb  = t >> 5;            // 0..7 (r adds 8)

    // smem: [buf][j*324 + row*20 + e], row = b or h. padded for banks + 16B align.
    __shared__ float xs[2][8 * 324];
    __shared__ float ws[2][8 * 324];

    float4 px[2], pw[2];               // prefetch registers (2 slots/thread)

    // prefetch chunk 0
#pragma unroll
    for (int r = 0; r < 2; ++r) {
        const int b = pb + r * 8;
        const long off = (long)b * IE + (long)(j0 + pj) * NE + e0 + pe4 * 4;
        px[r] = *(const float4*)(x  + off);
        pw[r] = *(const float4*)(wv + ((long)b * IE + (long)(j0 + pj) * NE + e0 + pe4 * 4));
    }
    // store chunk 0, prefetch chunk 1
#pragma unroll
    for (int r = 0; r < 2; ++r) {
        const int row = pb + r * 8;
        *(float4*)&xs[0][pj * 324 + row * 20 + pe4 * 4] = px[r];
        *(float4*)&ws[0][pj * 324 + row * 20 + pe4 * 4] = pw[r];
    }
    {
#pragma unroll
        for (int r = 0; r < 2; ++r) {
            const int b = pb + r * 8;
            const long off = (long)b * IE + (long)(j0 + 8 + pj) * NE + e0 + pe4 * 4;
            px[r] = *(const float4*)(x  + off);
            pw[r] = *(const float4*)(wv + off);
        }
    }
    __syncthreads();

    float acc[4][4];
#pragma unroll
    for (int i = 0; i < 4; ++i)
#pragma unroll
        for (int k = 0; k < 4; ++k) acc[i][k] = 0.f;

#pragma unroll
    for (int c = 0; c < 8; ++c) {      // 8 chunks of 8 j
        const int buf = c & 1;
        // compute current chunk
#pragma unroll
        for (int j = 0; j < 8; ++j) {
            float xv[4], wv4[4];
#pragma unroll
            for (int i = 0; i < 4; ++i) xv[i]  = xs[buf][j * 324 + (b0 + i) * 20 + el];
#pragma unroll
            for (int k = 0; k < 4; ++k) wv4[k] = ws[buf][j * 324 + (h0 + k) * 20 + el];
#pragma unroll
            for (int i = 0; i < 4; ++i)
#pragma unroll
                for (int k = 0; k < 4; ++k)
                    acc[i][k] = fmaf(xv[i], wv4[k], acc[i][k]);
        }
        if (c < 7) {
            // store prefetched chunk c+1 into the other buffer
#pragma unroll
            for (int r = 0; r < 2; ++r) {
                const int row = pb + r * 8;
                *(float4*)&xs[buf ^ 1][pj * 324 + row * 20 + pe4 * 4] = px[r];
                *(float4*)&ws[buf ^ 1][pj * 324 + row * 20 + pe4 * 4] = pw[r];
            }
            if (c < 6) {
                // prefetch chunk c+2
#pragma unroll
                for (int r = 0; r < 2; ++r) {
                    const int b = pb + r * 8;
                    const long off = (long)b * IE + (long)(j0 + (c + 2) * 8 + pj) * NE + e0 + pe4 * 4;
                    px[r] = *(const float4*)(x  + off);
                    pw[r] = *(const float4*)(wv + off);
                }
            }
            __syncthreads();
        }
    }

    // writeout: 16 scalar STG, coalesced along e within each warp
#pragma unroll
    for (int i = 0; i < 4; ++i)
#pragma unroll
        for (int k = 0; k < 4; ++k)
            g_embp[js][((b0 + i) * NH + (h0 + k)) * NE + e0 + el] = acc[i][k];
}

// ---------------------------------------------------------------------------
// Kernel 2: out[m][n] += sum_k emb[m][k]*w[n][k]  (bias already in out)
// M=256, N=512, K=512. Tiles 32m x 64n, split-K=8 (K=64/block, single smem
// stage) -> grid 512, ~4 blocks/SM, one wave at ~50% occ (fix for occ=12%).
// A-load folds the 8 j-split emb partials. REDG atomicAdd epilogue.
// ---------------------------------------------------------------------------
__global__ __launch_bounds__(256) void gemm_kernel(const float* __restrict__ w,
                                                   float* __restrict__ out) {
    const int t   = threadIdx.x;
    const int bid = blockIdx.x;        // 512 = 8 mt x 8 nt x 8 kt
    const int kt  = bid & 7;
    const int nt  = (bid >> 3) & 7;
    const int mt  = bid >> 6;
    const int m0 = mt * 32, n0 = nt * 64, k0 = kt * 64;

    __shared__ __align__(16) float sa[64][36];  // [k][m]
    __shared__ __align__(16) float sb[64][68];  // [k][n]

    // A tile: 32m x 64k, folded over 8 partials (2 float4 slots/thread)
#pragma unroll
    for (int r = 0; r < 2; ++r) {
        const int lin = t + r * 256;        // 512 slots
        const int row = lin >> 4;           // m 0..31
        const int kq  = (lin & 15) * 4;
        const int aoff = (m0 + row) * NE + k0 + kq;
        float4 a = *(const float4*)&g_embp[0][aoff];
#pragma unroll
        for (int p = 1; p < JSPLIT; ++p) {
            const float4 v = *(const float4*)&g_embp[p][aoff];
            a.x += v.x; a.y += v.y; a.z += v.z; a.w += v.w;
        }
        sa[kq + 0][row] = a.x;
        sa[kq + 1][row] = a.y;
        sa[kq + 2][row] = a.z;
        sa[kq + 3][row] = a.w;
    }
    // B tile: 64n x 64k (4 float4 slots/thread)
#pragma unroll
    for (int r = 0; r < 4; ++r) {
        const int lin = t + r * 256;        // 1024 slots
        const int row = lin >> 4;           // n 0..63
        const int kq  = (lin & 15) * 4;
        const float4 b4 = *(const float4*)&w[(n0 + row) * NE + k0 + kq];
        sb[kq + 0][row] = b4.x;
        sb[kq + 1][row] = b4.y;
        sb[kq + 2][row] = b4.z;
        sb[kq + 3][row] = b4.w;
    }
    __syncthreads();

    const int tx = t & 15;   // n micro (4 wide)
    const int ty = t >> 4;   // m micro (2 wide)
    float acc[2][4];
#pragma unroll
    for (int i = 0; i < 2; ++i)
#pragma unroll
        for (int j = 0; j < 4; ++j) acc[i][j] = 0.f;

#pragma unroll 8
    for (int kk = 0; kk < 64; ++kk) {
        const float2 av = *(const float2*)&sa[kk][ty * 2];
        const float4 bv = *(const float4*)&sb[kk][tx * 4];
        const float a2[2] = {av.x, av.y};
        const float b4[4] = {bv.x, bv.y, bv.z, bv.w};
#pragma unroll
        for (int i = 0; i < 2; ++i)
#pragma unroll
            for (int j = 0; j < 4; ++j)
                acc[i][j] = fmaf(a2[i], b4[j], acc[i][j]);
    }

    // Split-K accumulate into the bias-initialized output.
#pragma unroll
    for (int i = 0; i < 2; ++i) {
        float* op = &out[(m0 + ty * 2 + i) * NE + n0 + tx * 4];
#pragma unroll
        for (int j = 0; j < 4; ++j)
            atomicAdd(op + j, acc[i][j]);
    }
}

extern "C" void kernel_launch(void* const* d_in, const int* in_sizes, int n_in,
                              void* d_out, int out_size) {
    const float* x    = (const float*)d_in[0];  // [16,1,512,512]
    // d_in[1] = W_q, d_in[2] = W_k: mathematically dead (softmax cols sum to 1)
    const float* wv   = (const float*)d_in[3];  // [1,16,512,512]
    const float* mlpw = (const float*)d_in[4];  // [512,512]
    const float* mlpb = (const float*)d_in[5];  // [512]
    float* out = (float*)d_out;                 // [16,16,512]

    emb_kernel<<<256, 256>>>(x, wv, mlpb, out);
    gemm_kernel<<<512, 256>>>(mlpw, out);
}

// round 8
// speedup vs baseline: 1.1853x; 1.1853x over previous
#include <cuda_runtime.h>

#define NB 16
#define NH 16
#define NI 512
#define NE 512
#define IE (NI * NE)
#define JSPLIT 4

// emb partials (device scratch; allocations forbidden)
__device__ float g_embp[JSPLIT][NB * NH * NE];  // 2 MB

// ---------------------------------------------------------------------------
// Kernel 1: emb partials. g_embp[js][b,h,e] = sum_{j in 128-slice} x*Wv
// R4's proven scalar core: block = 8b x 8h x 32e x 128j; 256 threads =
// 32 e-lanes x 8 j-slices; per j: 16 broadcast LDG.32 + 64 FMA into an
// 8x8 register tile. Grid 256 = 16ec x 2hg x 2bg x 4js -> one wave at
// 2 blocks/SM. Also bias-inits the output (gemm accumulates on top).
// ---------------------------------------------------------------------------
__global__ __launch_bounds__(256) void emb_kernel(const float* __restrict__ x,
                                                  const float* __restrict__ wv,
                                                  const float* __restrict__ bias,
                                                  float* __restrict__ out) {
    const int t   = threadIdx.x;
    const int bid = blockIdx.x;        // 256 blocks

    // Bias init of the output.
    {
        const int oidx = bid * 256 + t;            // 0 .. 65535
        const float bv = bias[oidx & (NE - 1)];
        out[oidx]         = bv;
        out[oidx + 65536] = bv;
    }

    const int el  = t & 31;            // e lane (coalesced)
    const int sl  = t >> 5;            // j slice (warp id) 0..7
    const int ec  = bid & 15;          // e chunk 0..15
    const int hg  = (bid >> 4) & 1;    // h half
    const int bg  = (bid >> 5) & 1;    // b half
    const int js  = bid >> 6;          // j split 0..3

    const int e = ec * 32 + el;
    const float* xp = x  + bg * 8 * IE + e;
    const float* wp = wv + hg * 8 * IE + e;

    float acc[8][8];
#pragma unroll
    for (int i = 0; i < 8; ++i)
#pragma unroll
        for (int k = 0; k < 8; ++k) acc[i][k] = 0.f;

    const int j0 = js * 128;
#pragma unroll 2
    for (int jj = 0; jj < 16; ++jj) {
        const int joff = (j0 + sl + jj * 8) * NE;
        float xv[8], wv8[8];
#pragma unroll
        for (int i = 0; i < 8; ++i) xv[i]  = __ldg(xp + i * IE + joff);
#pragma unroll
        for (int k = 0; k < 8; ++k) wv8[k] = __ldg(wp + k * IE + joff);
#pragma unroll
        for (int i = 0; i < 8; ++i)
#pragma unroll
            for (int k = 0; k < 8; ++k)
                acc[i][k] = fmaf(xv[i], wv8[k], acc[i][k]);
    }

    __shared__ float red[8][32][32];   // [slice][ik][el] - conflict-free both ways
    const int b0 = bg * 8, h0 = hg * 8;
#pragma unroll
    for (int half = 0; half < 2; ++half) {
        __syncthreads();
#pragma unroll
        for (int ik = 0; ik < 32; ++ik) {
            const int ikf = half * 32 + ik;
            red[sl][ik][el] = acc[ikf >> 3][ikf & 7];
        }
        __syncthreads();
#pragma unroll
        for (int r = 0; r < 4; ++r) {
            const int ik = r * 8 + sl;
            float s = 0.f;
#pragma unroll
            for (int q = 0; q < 8; ++q) s += red[q][ik][el];
            const int ikf = half * 32 + ik;
            const int b = b0 + (ikf >> 3);
            const int h = h0 + (ikf & 7);
            g_embp[js][(b * NH + h) * NE + e] = s;
        }
    }
}

// ---------------------------------------------------------------------------
// Kernel 2: out[m][n] += sum_k emb[m][k]*w[n][k]  (bias already in out)
// R5's gemm verbatim (best measured: 13.6us cold). M=256, N=512, K=512.
// Tiles 64x64, split-K=4 (two 64-k smem stages) -> grid 128. A-load folds
// the 4 j-split partials. REDG atomicAdd epilogue.
// ---------------------------------------------------------------------------
__global__ __launch_bounds__(256) void gemm_kernel(const float* __restrict__ w,
                                                   float* __restrict__ out) {
    const int t   = threadIdx.x;
    const int bid = blockIdx.x;        // 128 = 4 mt x 8 nt x 4 kt
    const int kt  = bid & 3;
    const int nt  = (bid >> 2) & 7;
    const int mt  = bid >> 5;
    const int m0 = mt * 64, n0 = nt * 64;

    __shared__ __align__(16) float sa[64][68];  // [k][m]
    __shared__ __align__(16) float sb[64][68];  // [k][n]

    const int tx = t & 15;   // n micro-tile
    const int ty = t >> 4;   // m micro-tile
    float acc[4][4];
#pragma unroll
    for (int i = 0; i < 4; ++i)
#pragma unroll
        for (int j = 0; j < 4; ++j) acc[i][j] = 0.f;

#pragma unroll
    for (int kc = 0; kc < 2; ++kc) {
        const int k0 = kt * 128 + kc * 64;
        if (kc) __syncthreads();   // previous chunk's compute done before reload

#pragma unroll
        for (int r = 0; r < 4; ++r) {
            const int lin = t + r * 256;        // 0..1023 float4 slots
            const int row = lin >> 4;           // 0..63
            const int kq  = (lin & 15) * 4;     // 0..60
            const int aoff = (m0 + row) * NE + k0 + kq;
            float4 a = *(const float4*)&g_embp[0][aoff];
#pragma unroll
            for (int p = 1; p < JSPLIT; ++p) {
                const float4 v = *(const float4*)&g_embp[p][aoff];
                a.x += v.x; a.y += v.y; a.z += v.z; a.w += v.w;
            }
            sa[kq + 0][row] = a.x;
            sa[kq + 1][row] = a.y;
            sa[kq + 2][row] = a.z;
            sa[kq + 3][row] = a.w;
            const float4 b4 = *(const float4*)&w[(n0 + row) * NE + k0 + kq];
            sb[kq + 0][row] = b4.x;
            sb[kq + 1][row] = b4.y;
            sb[kq + 2][row] = b4.z;
            sb[kq + 3][row] = b4.w;
        }
        __syncthreads();

#pragma unroll 8
        for (int kk = 0; kk < 64; ++kk) {
            const float4 av = *(const float4*)&sa[kk][ty * 4];
            const float4 bv = *(const float4*)&sb[kk][tx * 4];
            const float a[4] = {av.x, av.y, av.z, av.w};
            const float b[4] = {bv.x, bv.y, bv.z, bv.w};
#pragma unroll
            for (int i = 0; i < 4; ++i)
#pragma unroll
                for (int j = 0; j < 4; ++j)
                    acc[i][j] = fmaf(a[i], b[j], acc[i][j]);
        }
    }

    // Split-K accumulate directly into the bias-initialized output.
#pragma unroll
    for (int i = 0; i < 4; ++i) {
        float* op = &out[(m0 + ty * 4 + i) * NE + n0 + tx * 4];
#pragma unroll
        for (int j = 0; j < 4; ++j)
            atomicAdd(op + j, acc[i][j]);
    }
}

extern "C" void kernel_launch(void* const* d_in, const int* in_sizes, int n_in,
                              void* d_out, int out_size) {
    const float* x    = (const float*)d_in[0];  // [16,1,512,512]
    // d_in[1] = W_q, d_in[2] = W_k: mathematically dead (softmax cols sum to 1)
    const float* wv   = (const float*)d_in[3];  // [1,16,512,512]
    const float* mlpw = (const float*)d_in[4];  // [512,512]
    const float* mlpb = (const float*)d_in[5];  // [512]
    float* out = (float*)d_out;                 // [16,16,512]

    emb_kernel<<<256, 256>>>(x, wv, mlpb, out);
    gemm_kernel<<<128, 256>>>(mlpw, out);
}